// round 8
// baseline (speedup 1.0000x reference)
#include <cuda_runtime.h>
#include <stdint.h>

#define B_   32
#define CI_  256
#define H_   56
#define W_   56
#define HW_  3136
#define CO_  256
#define HP_  58
#define WP_  58

// ---------------- scratch (__device__ globals: allocation-free rule) -------
// g_xpad: NHWC padded signs, PRE-SWIZZLED: 16B-chunk index ch stored at
//         ch ^ (lp & 7), lp = hp*58 + wp (per-batch padded pixel index).
__device__ int8_t g_xpad[(size_t)B_ * HP_ * WP_ * CI_];
// g_wsign: 36 pre-swizzled 16KB tiles: [coHalf][tap][ciHalf]
__device__ int8_t g_wsign[9 * CO_ * CI_];
__device__ float  g_coeff[CO_];

// ---------------- helpers ---------------------------------------------------
__device__ __forceinline__ uint32_t s2u(const void* p) {
    uint32_t a;
    asm("{ .reg .u64 t; cvta.to.shared.u64 t, %1; cvt.u32.u64 %0, t; }"
        : "=r"(a) : "l"(p));
    return a;
}
__device__ __forceinline__ void imma(int* c, const uint32_t* a, uint32_t b0, uint32_t b1) {
    asm volatile(
        "mma.sync.aligned.m16n8k32.row.col.s32.s8.s8.s32 "
        "{%0,%1,%2,%3}, {%4,%5,%6,%7}, {%8,%9}, {%0,%1,%2,%3};"
        : "+r"(c[0]), "+r"(c[1]), "+r"(c[2]), "+r"(c[3])
        : "r"(a[0]), "r"(a[1]), "r"(a[2]), "r"(a[3]), "r"(b0), "r"(b1));
}
__device__ __forceinline__ void ldm4(uint32_t* r, uint32_t addr) {
    asm volatile("ldmatrix.sync.aligned.m8n8.x4.shared.b16 {%0,%1,%2,%3}, [%4];"
                 : "=r"(r[0]), "=r"(r[1]), "=r"(r[2]), "=r"(r[3]) : "r"(addr));
}
__device__ __forceinline__ void mbar_init(uint32_t mb, uint32_t cnt) {
    asm volatile("mbarrier.init.shared.b64 [%0], %1;" :: "r"(mb), "r"(cnt) : "memory");
}
__device__ __forceinline__ void mbar_expect(uint32_t mb, uint32_t tx) {
    asm volatile("mbarrier.arrive.expect_tx.shared.b64 _, [%0], %1;"
                 :: "r"(mb), "r"(tx) : "memory");
}
__device__ __forceinline__ void bulk_g2s(uint32_t dst, const void* src, uint32_t bytes,
                                         uint32_t mb) {
    asm volatile(
        "cp.async.bulk.shared::cluster.global.mbarrier::complete_tx::bytes "
        "[%0], [%1], %2, [%3];"
        :: "r"(dst), "l"(src), "r"(bytes), "r"(mb) : "memory");
}
__device__ __forceinline__ void mbar_wait(uint32_t mb, uint32_t par) {
    asm volatile(
        "{\n\t"
        ".reg .pred P;\n\t"
        "WL%=:\n\t"
        "mbarrier.try_wait.parity.acquire.cta.shared::cta.b64 P, [%0], %1, 0x989680;\n\t"
        "@P bra WD%=;\n\t"
        "bra WL%=;\n\t"
        "WD%=:\n\t"
        "}" :: "r"(mb), "r"(par) : "memory");
}

// ---------------- kernel A: weights -> pre-swizzled int8 tiles + coeff ------
__global__ void prep_weights(const float* __restrict__ w,
                             const float* __restrict__ rv,
                             const float* __restrict__ alpha) {
    int co = blockIdx.x, ci = threadIdx.x;
    float r0 = rv[0], r1 = rv[1], r2 = rv[2], r3 = rv[3];
    const size_t ks = (size_t)CO_ * CI_ * 9;
    const float* p = w + ((size_t)co * CI_ + ci) * 9;
    int coH = co >> 7, r = co & 127;
    int cih = ci >> 7, cil = ci & 127, e = cil >> 4, byy = cil & 15;
    uint32_t toff = r * 128 + ((e ^ (r & 7)) << 4) + byy;
    float asum = 0.f;
#pragma unroll
    for (int t = 0; t < 9; t++) {
        float v = r0 * p[t] + r1 * p[ks + t] + r2 * p[2 * ks + t] + r3 * p[3 * ks + t];
        asum += fabsf(v);
        g_wsign[((size_t)((coH * 9 + t) * 2 + cih)) * 16384 + toff] =
            v > 0.f ? 1 : (v < 0.f ? -1 : 0);
    }
    __shared__ float red[256];
    red[ci] = asum;
    __syncthreads();
    for (int s = 128; s > 0; s >>= 1) {
        if (ci < s) red[ci] += red[ci + s];
        __syncthreads();
    }
    if (ci == 0) g_coeff[co] = alpha[co] * (red[0] / 2304.0f);
}

// ---------------- kernel B0: zero the pad ring (zeros: swizzle-invariant) ---
__global__ void zero_pad() {
    int b = blockIdx.y, i = blockIdx.x, t = threadIdx.x;
    int r, c;
    if (i < 58)       { r = 0;  c = i; }
    else if (i < 116) { r = 57; c = i - 58; }
    else { int j = i - 116; r = 1 + (j >> 1); c = (j & 1) * 57; }
    uint2* dst = (uint2*)&g_xpad[(((size_t)b * HP_ + r) * WP_ + c) * CI_];
    dst[t] = make_uint2(0, 0);
}

// ---------------- kernel B1: NCHW f32 -> pre-swizzled NHWC int8 signs -------
__global__ void pack_x(const float* __restrict__ x) {
    __shared__ uint32_t tile[32][65];
    int b = blockIdx.y;
    int hw0 = blockIdx.x * 32;
    int tid = threadIdx.x;
    int tx = tid & 31, ty = tid >> 5;
    const float* xp = x + (size_t)b * CI_ * HW_ + hw0 + tx;
#pragma unroll
    for (int k4 = 0; k4 < 8; k4++) {
        uint32_t pk = 0;
#pragma unroll
        for (int j = 0; j < 4; j++) {
            int ci = ty * 32 + k4 * 4 + j;
            float v = xp[(size_t)ci * HW_];
            int8_t s = v > 0.f ? 1 : (v < 0.f ? -1 : 0);
            pk |= ((uint32_t)(uint8_t)s) << (8 * j);
        }
        tile[tx][ty * 8 + k4] = pk;
    }
    __syncthreads();
    int p = tid >> 3, c8 = tid & 7;
    int hw = hw0 + p;
    int r = hw / 56, c = hw - r * 56;
    int lp = (r + 1) * 58 + (c + 1);
    int k = lp & 7;
    int8_t* base = &g_xpad[((size_t)b * (HP_ * WP_) + lp) * CI_];
    uint4 u0 = make_uint4(tile[p][c8 * 8 + 0], tile[p][c8 * 8 + 1],
                          tile[p][c8 * 8 + 2], tile[p][c8 * 8 + 3]);
    uint4 u1 = make_uint4(tile[p][c8 * 8 + 4], tile[p][c8 * 8 + 5],
                          tile[p][c8 * 8 + 6], tile[p][c8 * 8 + 7]);
    *(uint4*)(base + (((c8 * 2)     ^ k) << 4)) = u0;
    *(uint4*)(base + (((c8 * 2 + 1) ^ k) << 4)) = u1;
}

// ---------------- kernel C: A-resident, BOTH co-halves per CTA, 2 CTAs/SM ---
// CTA: 256 thr, 8 warps (2m x 4n), warp tile 64x32.
// M=128 px (2 rows x 56 + 16 dup). One A load serves 36 B chunks
// (coHalf 0: chunks 0..17, coHalf 1: 18..35). Mid-point epilogue overlaps
// the in-flight B prefetches for the second half.
#define A_SZ   59392              // 232*256
#define STG    16384
#define CF_OFF (A_SZ + 3 * STG)
#define MB_OFF (CF_OFF + 1024)
#define SMEM_DYN (MB_OFF + 64)    // ~110KB -> 2 CTAs/SM

__global__ void __launch_bounds__(256, 2) bconv_imma(float* __restrict__ out) {
    extern __shared__ char smem[];
    uint32_t sbA = s2u(smem);
    uint32_t mbA = sbA + MB_OFF;
    int tid = threadIdx.x, wid = tid >> 5, lane = tid & 31;
    int g = lane >> 2, tg = lane & 3;
    int wm = wid >> 2, wn = wid & 3;
    int r0 = blockIdx.x * 2, b = blockIdx.y;

    if (tid == 0) {
        mbar_init(mbA, 1);
        for (int s = 0; s < 3; s++) mbar_init(mbA + 8 + 8 * s, 1);
    }
    float* cf = (float*)(smem + CF_OFF);
    if (tid < 256) cf[tid] = g_coeff[tid];
    __syncthreads();

    if (tid == 0) {
        const int8_t* gA = &g_xpad[((size_t)b * (HP_ * WP_) + r0 * WP_) * CI_];
        mbar_expect(mbA, A_SZ);
        bulk_g2s(sbA, gA, A_SZ, mbA);
#pragma unroll
        for (int s = 0; s < 2; s++) {       // chunks 0,1 (coHalf 0, tap 0)
            const int8_t* gB = &g_wsign[(size_t)s * 16384];
            mbar_expect(mbA + 8 + 8 * s, STG);
            bulk_g2s(sbA + A_SZ + s * STG, gB, STG, mbA + 8 + 8 * s);
        }
    }

    // per-lane fragment geometry
    int t8 = lane >> 3, lr = lane & 7;
    int khalf = t8 >> 1, rsel = (t8 & 1) * 8;
    int lin0[4];
#pragma unroll
    for (int mf = 0; mf < 4; mf++) {
        int m = wm * 64 + mf * 16 + rsel + lr;
        if (m < 112) { int j = m >= 56; lin0[mf] = j * 58 + (m - (j ? 56 : 0)); }
        else lin0[mf] = 0;
    }
    int xadd = 2 * r0;                       // (r0*58) mod 8 == 2*r0 mod 8
    int rowB0 = wn * 32 + rsel + lr;
    int rowB1 = rowB0 + 16;
    uint32_t bB0 = rowB0 * 128 + A_SZ, bB1 = rowB1 * 128 + A_SZ;
    int xB0 = rowB0 & 7, xB1 = rowB1 & 7;

    int acc[4][4][4];
#pragma unroll
    for (int mf = 0; mf < 4; mf++)
#pragma unroll
        for (int nf = 0; nf < 4; nf++)
#pragma unroll
            for (int e = 0; e < 4; e++) acc[mf][nf][e] = 0;

    // epilogue writer (runs twice: cH = 0, 1)
    float* obase = out + (size_t)b * CO_ * HW_;
    auto epilogue = [&](int cH) {
#pragma unroll
        for (int mf = 0; mf < 4; mf++) {
#pragma unroll
            for (int half = 0; half < 2; half++) {
                int px = wm * 64 + mf * 16 + g + 8 * half;
                if (px < 112) {
                    int j = px >= 56;
                    int h = r0 + j;
                    int w = px - (j ? 56 : 0);
#pragma unroll
                    for (int nf = 0; nf < 4; nf++) {
                        int cl = cH * 128 + wn * 32 + nf * 8 + tg * 2;
                        float* o = obase + (size_t)cl * HW_ + h * 56 + w;
                        o[0]   = cf[cl]     * (float)acc[mf][nf][half * 2];
                        o[HW_] = cf[cl + 1] * (float)acc[mf][nf][half * 2 + 1];
                    }
                }
            }
        }
    };

    mbar_wait(mbA, 0);                        // A resident

    for (int cnt = 0; cnt < 36; cnt++) {
        // producer: chunk cnt+2 into stage (cnt+2)%3 (freed by sync of cnt-1)
        if (tid == 0 && cnt + 2 < 36) {
            int nc = cnt + 2, s = nc % 3;
            int cH = nc >= 18;
            int ii = nc - cH * 18;
            int tap = ii >> 1, cih = ii & 1;
            const int8_t* gB =
                &g_wsign[((size_t)((cH * 9 + tap) * 2 + cih)) * 16384];
            mbar_expect(mbA + 8 + 8 * s, STG);
            bulk_g2s(sbA + A_SZ + s * STG, gB, STG, mbA + 8 + 8 * s);
        }
        mbar_wait(mbA + 8 + 8 * (cnt % 3), (cnt / 3) & 1);

        int ii = cnt >= 18 ? cnt - 18 : cnt;
        int tap = ii >> 1, cihalf = ii & 1;
        int kh = tap / 3, kw = tap - kh * 3;
        int dlin = kh * 58 + kw;
        uint32_t aBase[4]; int x7[4];
#pragma unroll
        for (int mf = 0; mf < 4; mf++) {
            int lin = lin0[mf] + dlin;
            aBase[mf] = sbA + lin * 256;
            x7[mf] = (lin + xadd) & 7;
        }
        uint32_t bS = sbA + (cnt % 3) * STG;

#pragma unroll
        for (int s = 0; s < 4; s++) {
            int c16a = cihalf * 8 + s * 2 + khalf;
            int c16b = s * 2 + khalf;
            uint32_t a[4][4], bb[2][4];
#pragma unroll
            for (int mf = 0; mf < 4; mf++)
                ldm4(a[mf], aBase[mf] + ((c16a ^ x7[mf]) << 4));
            ldm4(bb[0], bS + bB0 + ((c16b ^ xB0) << 4));
            ldm4(bb[1], bS + bB1 + ((c16b ^ xB1) << 4));
#pragma unroll
            for (int mf = 0; mf < 4; mf++)
#pragma unroll
                for (int p = 0; p < 2; p++) {
                    imma(acc[mf][2 * p],     a[mf], bb[p][0], bb[p][2]);
                    imma(acc[mf][2 * p + 1], a[mf], bb[p][1], bb[p][3]);
                }
        }

        __syncthreads();   // stage (cnt%3) reusable

        if (cnt == 17) {   // half-0 done: store + reset while B prefetch runs
            epilogue(0);
#pragma unroll
            for (int mf = 0; mf < 4; mf++)
#pragma unroll
                for (int nf = 0; nf < 4; nf++)
#pragma unroll
                    for (int e = 0; e < 4; e++) acc[mf][nf][e] = 0;
        }
    }

    epilogue(1);
}

// ---------------------------------------------------------------------------
extern "C" void kernel_launch(void* const* d_in, const int* in_sizes, int n_in,
                              void* d_out, int out_size) {
    const float *x = nullptr, *wt = nullptr, *rv = nullptr, *al = nullptr;
    for (int i = 0; i < n_in; i++) {
        switch (in_sizes[i]) {
            case 25690112: x  = (const float*)d_in[i]; break;
            case 2359296:  wt = (const float*)d_in[i]; break;
            case 5:        rv = (const float*)d_in[i]; break;
            case 256:      al = (const float*)d_in[i]; break;
        }
    }

    prep_weights<<<256, 256>>>(wt, rv, al);

    dim3 gz(228, 32);
    zero_pad<<<gz, 32>>>();

    dim3 gp(98, 32);
    pack_x<<<gp, 32 * 8>>>(x);

    static int smem_set = 0;
    if (!smem_set) {
        cudaFuncSetAttribute(bconv_imma, cudaFuncAttributeMaxDynamicSharedMemorySize,
                             SMEM_DYN);
        smem_set = 1;
    }
    dim3 gc(28, 32);
    bconv_imma<<<gc, 256, SMEM_DYN>>>((float*)d_out);
}

// round 9
// speedup vs baseline: 1.0472x; 1.0472x over previous
#include <cuda_runtime.h>
#include <stdint.h>

#define B_   32
#define CI_  256
#define H_   56
#define W_   56
#define HW_  3136
#define CO_  256
#define HP_  58
#define WP_  58

// ---------------- scratch (__device__ globals: allocation-free rule) -------
// g_xpad: NHWC padded signs, PRE-SWIZZLED: 16B-chunk index ch stored at
//         ch ^ (lp & 7), lp = hp*58 + wp (per-batch padded pixel index).
__device__ int8_t g_xpad[(size_t)B_ * HP_ * WP_ * CI_];
// g_wsign: 36 pre-swizzled 16KB tiles: [coHalf][tap][ciHalf]
__device__ int8_t g_wsign[9 * CO_ * CI_];
__device__ float  g_coeff[CO_];

// ---------------- helpers ---------------------------------------------------
__device__ __forceinline__ uint32_t s2u(const void* p) {
    uint32_t a;
    asm("{ .reg .u64 t; cvta.to.shared.u64 t, %1; cvt.u32.u64 %0, t; }"
        : "=r"(a) : "l"(p));
    return a;
}
__device__ __forceinline__ void imma(int* c, const uint32_t* a, uint32_t b0, uint32_t b1) {
    asm volatile(
        "mma.sync.aligned.m16n8k32.row.col.s32.s8.s8.s32 "
        "{%0,%1,%2,%3}, {%4,%5,%6,%7}, {%8,%9}, {%0,%1,%2,%3};"
        : "+r"(c[0]), "+r"(c[1]), "+r"(c[2]), "+r"(c[3])
        : "r"(a[0]), "r"(a[1]), "r"(a[2]), "r"(a[3]), "r"(b0), "r"(b1));
}
__device__ __forceinline__ void ldm4(uint32_t* r, uint32_t addr) {
    asm volatile("ldmatrix.sync.aligned.m8n8.x4.shared.b16 {%0,%1,%2,%3}, [%4];"
                 : "=r"(r[0]), "=r"(r[1]), "=r"(r[2]), "=r"(r[3]) : "r"(addr));
}
__device__ __forceinline__ void mbar_init(uint32_t mb, uint32_t cnt) {
    asm volatile("mbarrier.init.shared.b64 [%0], %1;" :: "r"(mb), "r"(cnt) : "memory");
}
__device__ __forceinline__ void mbar_expect(uint32_t mb, uint32_t tx) {
    asm volatile("mbarrier.arrive.expect_tx.shared.b64 _, [%0], %1;"
                 :: "r"(mb), "r"(tx) : "memory");
}
__device__ __forceinline__ void mbar_arrive(uint32_t mb) {
    asm volatile("mbarrier.arrive.release.cta.shared.b64 _, [%0];"
                 :: "r"(mb) : "memory");
}
__device__ __forceinline__ void bulk_g2s(uint32_t dst, const void* src, uint32_t bytes,
                                         uint32_t mb) {
    asm volatile(
        "cp.async.bulk.shared::cluster.global.mbarrier::complete_tx::bytes "
        "[%0], [%1], %2, [%3];"
        :: "r"(dst), "l"(src), "r"(bytes), "r"(mb) : "memory");
}
__device__ __forceinline__ void mbar_wait(uint32_t mb, uint32_t par) {
    asm volatile(
        "{\n\t"
        ".reg .pred P;\n\t"
        "WL%=:\n\t"
        "mbarrier.try_wait.parity.acquire.cta.shared::cta.b64 P, [%0], %1, 0x989680;\n\t"
        "@P bra WD%=;\n\t"
        "bra WL%=;\n\t"
        "WD%=:\n\t"
        "}" :: "r"(mb), "r"(par) : "memory");
}

// ---------------- kernel A: weights -> pre-swizzled int8 tiles + coeff ------
__global__ void prep_weights(const float* __restrict__ w,
                             const float* __restrict__ rv,
                             const float* __restrict__ alpha) {
    int co = blockIdx.x, ci = threadIdx.x;
    float r0 = rv[0], r1 = rv[1], r2 = rv[2], r3 = rv[3];
    const size_t ks = (size_t)CO_ * CI_ * 9;
    const float* p = w + ((size_t)co * CI_ + ci) * 9;
    int coH = co >> 7, r = co & 127;
    int cih = ci >> 7, cil = ci & 127, e = cil >> 4, byy = cil & 15;
    uint32_t toff = r * 128 + ((e ^ (r & 7)) << 4) + byy;
    float asum = 0.f;
#pragma unroll
    for (int t = 0; t < 9; t++) {
        float v = r0 * p[t] + r1 * p[ks + t] + r2 * p[2 * ks + t] + r3 * p[3 * ks + t];
        asum += fabsf(v);
        g_wsign[((size_t)((coH * 9 + t) * 2 + cih)) * 16384 + toff] =
            v > 0.f ? 1 : (v < 0.f ? -1 : 0);
    }
    __shared__ float red[256];
    red[ci] = asum;
    __syncthreads();
    for (int s = 128; s > 0; s >>= 1) {
        if (ci < s) red[ci] += red[ci + s];
        __syncthreads();
    }
    if (ci == 0) g_coeff[co] = alpha[co] * (red[0] / 2304.0f);
}

// ---------------- kernel B0: zero the pad ring (zeros: swizzle-invariant) ---
__global__ void zero_pad() {
    int b = blockIdx.y, i = blockIdx.x, t = threadIdx.x;
    int r, c;
    if (i < 58)       { r = 0;  c = i; }
    else if (i < 116) { r = 57; c = i - 58; }
    else { int j = i - 116; r = 1 + (j >> 1); c = (j & 1) * 57; }
    uint2* dst = (uint2*)&g_xpad[(((size_t)b * HP_ + r) * WP_ + c) * CI_];
    dst[t] = make_uint2(0, 0);
}

// ---------------- kernel B1: NCHW f32 -> pre-swizzled NHWC int8 signs -------
__global__ void pack_x(const float* __restrict__ x) {
    __shared__ uint32_t tile[32][65];
    int b = blockIdx.y;
    int hw0 = blockIdx.x * 32;
    int tid = threadIdx.x;
    int tx = tid & 31, ty = tid >> 5;
    const float* xp = x + (size_t)b * CI_ * HW_ + hw0 + tx;
#pragma unroll
    for (int k4 = 0; k4 < 8; k4++) {
        uint32_t pk = 0;
#pragma unroll
        for (int j = 0; j < 4; j++) {
            int ci = ty * 32 + k4 * 4 + j;
            float v = xp[(size_t)ci * HW_];
            int8_t s = v > 0.f ? 1 : (v < 0.f ? -1 : 0);
            pk |= ((uint32_t)(uint8_t)s) << (8 * j);
        }
        tile[tx][ty * 8 + k4] = pk;
    }
    __syncthreads();
    int p = tid >> 3, c8 = tid & 7;
    int hw = hw0 + p;
    int r = hw / 56, c = hw - r * 56;
    int lp = (r + 1) * 58 + (c + 1);
    int k = lp & 7;
    int8_t* base = &g_xpad[((size_t)b * (HP_ * WP_) + lp) * CI_];
    uint4 u0 = make_uint4(tile[p][c8 * 8 + 0], tile[p][c8 * 8 + 1],
                          tile[p][c8 * 8 + 2], tile[p][c8 * 8 + 3]);
    uint4 u1 = make_uint4(tile[p][c8 * 8 + 4], tile[p][c8 * 8 + 5],
                          tile[p][c8 * 8 + 6], tile[p][c8 * 8 + 7]);
    *(uint4*)(base + (((c8 * 2)     ^ k) << 4)) = u0;
    *(uint4*)(base + (((c8 * 2 + 1) ^ k) << 4)) = u1;
}

// ---------------- kernel C: warp-decoupled producer/consumer IMMA conv ------
// Block 288 thr: warps 0..7 compute (2m x 4n grid, warp tile 64x32),
// warp 8 = producer (bulk copies). M=128 px (2 rows x 56 + 16 dup) x N=128.
// A: 58KB resident (1 bulk). B: 18 chunks x 16KB, 3-stage ring with
// full[s] (tx) / free[s] (8 warp arrivals) mbarriers. NO __syncthreads in loop.
#define A_SZ   59392              // 232*256
#define STG    16384
#define CF_OFF (A_SZ + 3 * STG)
#define MB_OFF (CF_OFF + 1024)
#define SMEM_DYN (MB_OFF + 128)   // ~110KB -> 2 CTAs/SM

__global__ void __launch_bounds__(288, 2) bconv_imma(float* __restrict__ out) {
    extern __shared__ char smem[];
    uint32_t sbA = s2u(smem);
    uint32_t mbA    = sbA + MB_OFF;        // A full barrier
    uint32_t mbFull = mbA + 8;             // full[0..2]
    uint32_t mbFree = mbA + 32;            // free[0..2]
    int tid = threadIdx.x, wid = tid >> 5, lane = tid & 31;
    int r0 = blockIdx.x * 2, coHalf = blockIdx.y, b = blockIdx.z;

    if (tid == 0) {
        mbar_init(mbA, 1);
        for (int s = 0; s < 3; s++) {
            mbar_init(mbFull + 8 * s, 1);
            mbar_init(mbFree + 8 * s, 8);
        }
    }
    float* cf = (float*)(smem + CF_OFF);
    if (tid < 128) cf[tid] = g_coeff[coHalf * 128 + tid];
    __syncthreads();

    if (wid == 8) {
        // ---------------- producer warp ----------------
        if (lane == 0) {
            const int8_t* gA = &g_xpad[((size_t)b * (HP_ * WP_) + r0 * WP_) * CI_];
            mbar_expect(mbA, A_SZ);
            bulk_g2s(sbA, gA, A_SZ, mbA);
            for (int nc = 0; nc < 18; nc++) {
                int s = nc % 3;
                if (nc >= 3) mbar_wait(mbFree + 8 * s, (nc / 3 - 1) & 1);
                int tap = nc >> 1, cih = nc & 1;
                const int8_t* gB =
                    &g_wsign[((size_t)((coHalf * 9 + tap) * 2 + cih)) * 16384];
                mbar_expect(mbFull + 8 * s, STG);
                bulk_g2s(sbA + A_SZ + s * STG, gB, STG, mbFull + 8 * s);
            }
        }
        return;
    }

    // ---------------- compute warps (0..7) ----------------
    int g = lane >> 2, tg = lane & 3;
    int wm = wid >> 2, wn = wid & 3;

    int t8 = lane >> 3, lr = lane & 7;
    int khalf = t8 >> 1, rsel = (t8 & 1) * 8;
    int lin0[4];
#pragma unroll
    for (int mf = 0; mf < 4; mf++) {
        int m = wm * 64 + mf * 16 + rsel + lr;
        if (m < 112) { int j = m >= 56; lin0[mf] = j * 58 + (m - (j ? 56 : 0)); }
        else lin0[mf] = 0;
    }
    int xadd = 2 * r0;                       // (r0*58) mod 8
    int rowB0 = wn * 32 + rsel + lr;
    int rowB1 = rowB0 + 16;
    uint32_t bB0 = rowB0 * 128 + A_SZ, bB1 = rowB1 * 128 + A_SZ;
    int xB0 = rowB0 & 7, xB1 = rowB1 & 7;

    int acc[4][4][4];
#pragma unroll
    for (int mf = 0; mf < 4; mf++)
#pragma unroll
        for (int nf = 0; nf < 4; nf++)
#pragma unroll
            for (int e = 0; e < 4; e++) acc[mf][nf][e] = 0;

    mbar_wait(mbA, 0);                       // A resident

    for (int i = 0; i < 18; i++) {
        mbar_wait(mbFull + 8 * (i % 3), (i / 3) & 1);

        int tap = i >> 1, cihalf = i & 1;
        int kh = tap / 3, kw = tap - kh * 3;
        int dlin = kh * 58 + kw;
        uint32_t aBase[4]; int x7[4];
#pragma unroll
        for (int mf = 0; mf < 4; mf++) {
            int lin = lin0[mf] + dlin;
            aBase[mf] = sbA + lin * 256;
            x7[mf] = (lin + xadd) & 7;
        }
        uint32_t bS = sbA + (i % 3) * STG;

#pragma unroll
        for (int s = 0; s < 4; s++) {
            int c16a = cihalf * 8 + s * 2 + khalf;
            int c16b = s * 2 + khalf;
            uint32_t a[4][4], bb[2][4];
#pragma unroll
            for (int mf = 0; mf < 4; mf++)
                ldm4(a[mf], aBase[mf] + ((c16a ^ x7[mf]) << 4));
            ldm4(bb[0], bS + bB0 + ((c16b ^ xB0) << 4));
            ldm4(bb[1], bS + bB1 + ((c16b ^ xB1) << 4));
#pragma unroll
            for (int mf = 0; mf < 4; mf++)
#pragma unroll
                for (int p = 0; p < 2; p++) {
                    imma(acc[mf][2 * p],     a[mf], bb[p][0], bb[p][2]);
                    imma(acc[mf][2 * p + 1], a[mf], bb[p][1], bb[p][3]);
                }
        }

        __syncwarp();
        if (lane == 0) mbar_arrive(mbFree + 8 * (i % 3));   // stage reusable
    }

    // ---- epilogue: out[b][co][h][w] = coeff[co] * acc (NCHW) ----
    float* obase = out + (size_t)b * CO_ * HW_;
#pragma unroll
    for (int mf = 0; mf < 4; mf++) {
#pragma unroll
        for (int half = 0; half < 2; half++) {
            int px = wm * 64 + mf * 16 + g + 8 * half;
            if (px < 112) {
                int j = px >= 56;
                int h = r0 + j;
                int w = px - (j ? 56 : 0);
#pragma unroll
                for (int nf = 0; nf < 4; nf++) {
                    int cl = wn * 32 + nf * 8 + tg * 2;
                    float* o = obase + (size_t)(coHalf * 128 + cl) * HW_ + h * 56 + w;
                    o[0]   = cf[cl]     * (float)acc[mf][nf][half * 2];
                    o[HW_] = cf[cl + 1] * (float)acc[mf][nf][half * 2 + 1];
                }
            }
        }
    }
}

// ---------------------------------------------------------------------------
extern "C" void kernel_launch(void* const* d_in, const int* in_sizes, int n_in,
                              void* d_out, int out_size) {
    const float *x = nullptr, *wt = nullptr, *rv = nullptr, *al = nullptr;
    for (int i = 0; i < n_in; i++) {
        switch (in_sizes[i]) {
            case 25690112: x  = (const float*)d_in[i]; break;
            case 2359296:  wt = (const float*)d_in[i]; break;
            case 5:        rv = (const float*)d_in[i]; break;
            case 256:      al = (const float*)d_in[i]; break;
        }
    }

    prep_weights<<<256, 256>>>(wt, rv, al);

    dim3 gz(228, 32);
    zero_pad<<<gz, 32>>>();

    dim3 gp(98, 32);
    pack_x<<<gp, 256>>>(x);

    static int smem_set = 0;
    if (!smem_set) {
        cudaFuncSetAttribute(bconv_imma, cudaFuncAttributeMaxDynamicSharedMemorySize,
                             SMEM_DYN);
        smem_set = 1;
    }
    dim3 gc(28, 2, 32);
    bconv_imma<<<gc, 288, SMEM_DYN>>>((float*)d_out);
}

// round 10
// speedup vs baseline: 1.2012x; 1.1471x over previous
#include <cuda_runtime.h>
#include <stdint.h>

#define B_   32
#define CI_  256
#define H_   56
#define W_   56
#define HW_  3136
#define CO_  256
#define HP_  58
#define WP_  58

// ---------------- scratch (__device__ globals: allocation-free rule) -------
// g_xpad: NHWC padded signs, PRE-SWIZZLED: 16B-chunk index ch stored at
//         ch ^ (lp & 7), lp = hp*58 + wp (per-batch padded pixel index).
__device__ int8_t g_xpad[(size_t)B_ * HP_ * WP_ * CI_];
// g_wsign: 36 pre-swizzled 16KB tiles: [coHalf][tap][ciHalf]
__device__ int8_t g_wsign[9 * CO_ * CI_];
__device__ float  g_coeff[CO_];

// ---------------- helpers ---------------------------------------------------
__device__ __forceinline__ uint32_t s2u(const void* p) {
    uint32_t a;
    asm("{ .reg .u64 t; cvta.to.shared.u64 t, %1; cvt.u32.u64 %0, t; }"
        : "=r"(a) : "l"(p));
    return a;
}
__device__ __forceinline__ void imma(int* c, const uint32_t* a, uint32_t b0, uint32_t b1) {
    asm volatile(
        "mma.sync.aligned.m16n8k32.row.col.s32.s8.s8.s32 "
        "{%0,%1,%2,%3}, {%4,%5,%6,%7}, {%8,%9}, {%0,%1,%2,%3};"
        : "+r"(c[0]), "+r"(c[1]), "+r"(c[2]), "+r"(c[3])
        : "r"(a[0]), "r"(a[1]), "r"(a[2]), "r"(a[3]), "r"(b0), "r"(b1));
}
__device__ __forceinline__ void ldm4(uint32_t* r, uint32_t addr) {
    asm volatile("ldmatrix.sync.aligned.m8n8.x4.shared.b16 {%0,%1,%2,%3}, [%4];"
                 : "=r"(r[0]), "=r"(r[1]), "=r"(r[2]), "=r"(r[3]) : "r"(addr));
}
__device__ __forceinline__ void mbar_init(uint32_t mb, uint32_t cnt) {
    asm volatile("mbarrier.init.shared.b64 [%0], %1;" :: "r"(mb), "r"(cnt) : "memory");
}
__device__ __forceinline__ void mbar_expect(uint32_t mb, uint32_t tx) {
    asm volatile("mbarrier.arrive.expect_tx.shared.b64 _, [%0], %1;"
                 :: "r"(mb), "r"(tx) : "memory");
}
__device__ __forceinline__ void bulk_g2s(uint32_t dst, const void* src, uint32_t bytes,
                                         uint32_t mb) {
    asm volatile(
        "cp.async.bulk.shared::cluster.global.mbarrier::complete_tx::bytes "
        "[%0], [%1], %2, [%3];"
        :: "r"(dst), "l"(src), "r"(bytes), "r"(mb) : "memory");
}
__device__ __forceinline__ void mbar_wait(uint32_t mb, uint32_t par) {
    asm volatile(
        "{\n\t"
        ".reg .pred P;\n\t"
        "WL%=:\n\t"
        "mbarrier.try_wait.parity.acquire.cta.shared::cta.b64 P, [%0], %1, 0x989680;\n\t"
        "@P bra WD%=;\n\t"
        "bra WL%=;\n\t"
        "WD%=:\n\t"
        "}" :: "r"(mb), "r"(par) : "memory");
}

// ---------------- kernel A: weights -> pre-swizzled int8 tiles + coeff ------
__global__ void prep_weights(const float* __restrict__ w,
                             const float* __restrict__ rv,
                             const float* __restrict__ alpha) {
    int co = blockIdx.x, ci = threadIdx.x;
    float r0 = rv[0], r1 = rv[1], r2 = rv[2], r3 = rv[3];
    const size_t ks = (size_t)CO_ * CI_ * 9;
    const float* p = w + ((size_t)co * CI_ + ci) * 9;
    int coH = co >> 7, r = co & 127;
    int cih = ci >> 7, cil = ci & 127, e = cil >> 4, byy = cil & 15;
    uint32_t toff = r * 128 + ((e ^ (r & 7)) << 4) + byy;
    float asum = 0.f;
#pragma unroll
    for (int t = 0; t < 9; t++) {
        float v = r0 * p[t] + r1 * p[ks + t] + r2 * p[2 * ks + t] + r3 * p[3 * ks + t];
        asum += fabsf(v);
        g_wsign[((size_t)((coH * 9 + t) * 2 + cih)) * 16384 + toff] =
            v > 0.f ? 1 : (v < 0.f ? -1 : 0);
    }
    __shared__ float red[256];
    red[ci] = asum;
    __syncthreads();
    for (int s = 128; s > 0; s >>= 1) {
        if (ci < s) red[ci] += red[ci + s];
        __syncthreads();
    }
    if (ci == 0) g_coeff[co] = alpha[co] * (red[0] / 2304.0f);
}

// ---------------- kernel B0: zero the pad ring (zeros: swizzle-invariant) ---
__global__ void zero_pad() {
    int b = blockIdx.y, i = blockIdx.x, t = threadIdx.x;
    int r, c;
    if (i < 58)       { r = 0;  c = i; }
    else if (i < 116) { r = 57; c = i - 58; }
    else { int j = i - 116; r = 1 + (j >> 1); c = (j & 1) * 57; }
    uint2* dst = (uint2*)&g_xpad[(((size_t)b * HP_ + r) * WP_ + c) * CI_];
    dst[t] = make_uint2(0, 0);
}

// ---------------- kernel B1: NCHW f32 -> pre-swizzled NHWC int8 signs -------
__global__ void pack_x(const float* __restrict__ x) {
    __shared__ uint32_t tile[32][65];
    int b = blockIdx.y;
    int hw0 = blockIdx.x * 32;
    int tid = threadIdx.x;
    int tx = tid & 31, ty = tid >> 5;
    const float* xp = x + (size_t)b * CI_ * HW_ + hw0 + tx;
#pragma unroll
    for (int k4 = 0; k4 < 8; k4++) {
        uint32_t pk = 0;
#pragma unroll
        for (int j = 0; j < 4; j++) {
            int ci = ty * 32 + k4 * 4 + j;
            float v = xp[(size_t)ci * HW_];
            int8_t s = v > 0.f ? 1 : (v < 0.f ? -1 : 0);
            pk |= ((uint32_t)(uint8_t)s) << (8 * j);
        }
        tile[tx][ty * 8 + k4] = pk;
    }
    __syncthreads();
    int p = tid >> 3, c8 = tid & 7;
    int hw = hw0 + p;
    int r = hw / 56, c = hw - r * 56;
    int lp = (r + 1) * 58 + (c + 1);
    int k = lp & 7;
    int8_t* base = &g_xpad[((size_t)b * (HP_ * WP_) + lp) * CI_];
    uint4 u0 = make_uint4(tile[p][c8 * 8 + 0], tile[p][c8 * 8 + 1],
                          tile[p][c8 * 8 + 2], tile[p][c8 * 8 + 3]);
    uint4 u1 = make_uint4(tile[p][c8 * 8 + 4], tile[p][c8 * 8 + 5],
                          tile[p][c8 * 8 + 6], tile[p][c8 * 8 + 7]);
    *(uint4*)(base + (((c8 * 2)     ^ k) << 4)) = u0;
    *(uint4*)(base + (((c8 * 2 + 1) ^ k) << 4)) = u1;
}

// ---------------- kernel C: asymmetric-M A-resident IMMA conv, 2 CTAs/SM ----
// CTA: 256 thr, 8 warps (2m x 4n). wm=0 warps: 4 m-frags (px 0..63);
// wm=1 warps: 3 m-frags (px 64..111). NO duplicate-row MACs.
// A: 58KB resident (1 bulk). B: 18 chunks x 16KB, 3-stage ring.
#define A_SZ   59392              // 232*256
#define STG    16384
#define CF_OFF (A_SZ + 3 * STG)
#define MB_OFF (CF_OFF + 512)
#define SMEM_DYN (MB_OFF + 64)    // ~110KB -> 2 CTAs/SM

// Slice loop for one 128-byte ci-chunk; MF = #m-fragments for this warp.
template <int MF>
__device__ __forceinline__ void slices(const uint32_t* aBase, const int* x7,
                                       uint32_t bS, uint32_t bB0, uint32_t bB1,
                                       int xB0, int xB1, int khalf, int cihalf,
                                       int acc[4][4][4]) {
#pragma unroll
    for (int s = 0; s < 4; s++) {
        int c16a = cihalf * 8 + s * 2 + khalf;
        int c16b = s * 2 + khalf;
        uint32_t a[MF][4], bb[2][4];
#pragma unroll
        for (int mf = 0; mf < MF; mf++)
            ldm4(a[mf], aBase[mf] + ((c16a ^ x7[mf]) << 4));
        ldm4(bb[0], bS + bB0 + ((c16b ^ xB0) << 4));
        ldm4(bb[1], bS + bB1 + ((c16b ^ xB1) << 4));
#pragma unroll
        for (int mf = 0; mf < MF; mf++)
#pragma unroll
            for (int p = 0; p < 2; p++) {
                imma(acc[mf][2 * p],     a[mf], bb[p][0], bb[p][2]);
                imma(acc[mf][2 * p + 1], a[mf], bb[p][1], bb[p][3]);
            }
    }
}

__global__ void __launch_bounds__(256, 2) bconv_imma(float* __restrict__ out) {
    extern __shared__ char smem[];
    uint32_t sbA = s2u(smem);
    uint32_t mbA = sbA + MB_OFF;
    int tid = threadIdx.x, wid = tid >> 5, lane = tid & 31;
    int g = lane >> 2, tg = lane & 3;
    int wm = wid >> 2, wn = wid & 3;
    int NMF = wm == 0 ? 4 : 3;
    int r0 = blockIdx.x * 2, coHalf = blockIdx.y, b = blockIdx.z;

    if (tid == 0) {
        mbar_init(mbA, 1);
        for (int s = 0; s < 3; s++) mbar_init(mbA + 8 + 8 * s, 1);
    }
    float* cf = (float*)(smem + CF_OFF);
    if (tid < 128) cf[tid] = g_coeff[coHalf * 128 + tid];
    __syncthreads();

    if (tid == 0) {
        const int8_t* gA = &g_xpad[((size_t)b * (HP_ * WP_) + r0 * WP_) * CI_];
        mbar_expect(mbA, A_SZ);
        bulk_g2s(sbA, gA, A_SZ, mbA);
#pragma unroll
        for (int s = 0; s < 2; s++) {
            const int8_t* gB = &g_wsign[((size_t)(coHalf * 9 * 2 + s)) * 16384];
            mbar_expect(mbA + 8 + 8 * s, STG);
            bulk_g2s(sbA + A_SZ + s * STG, gB, STG, mbA + 8 + 8 * s);
        }
    }

    // per-lane fragment geometry (all m in [0,112) now — no dup rows)
    int t8 = lane >> 3, lr = lane & 7;
    int khalf = t8 >> 1, rsel = (t8 & 1) * 8;
    int lin0[4];
#pragma unroll
    for (int mf = 0; mf < 4; mf++) {
        int m = wm * 64 + mf * 16 + rsel + lr;
        if (m < 112) { int j = m >= 56; lin0[mf] = j * 58 + (m - (j ? 56 : 0)); }
        else lin0[mf] = 0;
    }
    int xadd = 2 * r0;                       // (r0*58) mod 8
    int rowB0 = wn * 32 + rsel + lr;
    int rowB1 = rowB0 + 16;
    uint32_t bB0 = rowB0 * 128 + A_SZ, bB1 = rowB1 * 128 + A_SZ;
    int xB0 = rowB0 & 7, xB1 = rowB1 & 7;

    int acc[4][4][4];
#pragma unroll
    for (int mf = 0; mf < 4; mf++)
#pragma unroll
        for (int nf = 0; nf < 4; nf++)
#pragma unroll
            for (int e = 0; e < 4; e++) acc[mf][nf][e] = 0;

    mbar_wait(mbA, 0);                        // A resident

    for (int i = 0; i < 18; i++) {
        // producer: chunk i+2 into stage (i+2)%3 (slot freed by sync of i-1)
        if (tid == 0 && i + 2 < 18) {
            int nc = i + 2, s = nc % 3;
            int tap = nc >> 1, cih = nc & 1;
            const int8_t* gB =
                &g_wsign[((size_t)((coHalf * 9 + tap) * 2 + cih)) * 16384];
            mbar_expect(mbA + 8 + 8 * s, STG);
            bulk_g2s(sbA + A_SZ + s * STG, gB, STG, mbA + 8 + 8 * s);
        }
        mbar_wait(mbA + 8 + 8 * (i % 3), (i / 3) & 1);

        int tap = i >> 1, cihalf = i & 1;
        int kh = tap / 3, kw = tap - kh * 3;
        int dlin = kh * 58 + kw;
        uint32_t aBase[4]; int x7[4];
#pragma unroll
        for (int mf = 0; mf < 4; mf++) {
            int lin = lin0[mf] + dlin;
            aBase[mf] = sbA + lin * 256;
            x7[mf] = (lin + xadd) & 7;
        }
        uint32_t bS = sbA + (i % 3) * STG;

        if (wm == 0)
            slices<4>(aBase, x7, bS, bB0, bB1, xB0, xB1, khalf, cihalf, acc);
        else
            slices<3>(aBase, x7, bS, bB0, bB1, xB0, xB1, khalf, cihalf, acc);

        __syncthreads();   // stage (i%3) reusable
    }

    // ---- epilogue: out[b][co][h][w] = coeff[co] * acc (NCHW) ----
    float* obase = out + (size_t)b * CO_ * HW_;
#pragma unroll
    for (int mf = 0; mf < 4; mf++) {
        if (mf >= NMF) break;
#pragma unroll
        for (int half = 0; half < 2; half++) {
            int px = wm * 64 + mf * 16 + g + 8 * half;   // always < 112
            int j = px >= 56;
            int h = r0 + j;
            int w = px - (j ? 56 : 0);
#pragma unroll
            for (int nf = 0; nf < 4; nf++) {
                int cl = wn * 32 + nf * 8 + tg * 2;
                float* o = obase + (size_t)(coHalf * 128 + cl) * HW_ + h * 56 + w;
                o[0]   = cf[cl]     * (float)acc[mf][nf][half * 2];
                o[HW_] = cf[cl + 1] * (float)acc[mf][nf][half * 2 + 1];
            }
        }
    }
}

// ---------------------------------------------------------------------------
extern "C" void kernel_launch(void* const* d_in, const int* in_sizes, int n_in,
                              void* d_out, int out_size) {
    const float *x = nullptr, *wt = nullptr, *rv = nullptr, *al = nullptr;
    for (int i = 0; i < n_in; i++) {
        switch (in_sizes[i]) {
            case 25690112: x  = (const float*)d_in[i]; break;
            case 2359296:  wt = (const float*)d_in[i]; break;
            case 5:        rv = (const float*)d_in[i]; break;
            case 256:      al = (const float*)d_in[i]; break;
        }
    }

    prep_weights<<<256, 256>>>(wt, rv, al);

    dim3 gz(228, 32);
    zero_pad<<<gz, 32>>>();

    dim3 gp(98, 32);
    pack_x<<<gp, 256>>>(x);

    static int smem_set = 0;
    if (!smem_set) {
        cudaFuncSetAttribute(bconv_imma, cudaFuncAttributeMaxDynamicSharedMemorySize,
                             SMEM_DYN);
        smem_set = 1;
    }
    dim3 gc(28, 2, 32);
    bconv_imma<<<gc, 256, SMEM_DYN>>>((float*)d_out);
}